// round 4
// baseline (speedup 1.0000x reference)
#include <cuda_runtime.h>
#include <cstdint>

// ---------------------------------------------------------------------------
// QuanvolutionSamplerHybrid — closed-form circuit, f32x2 patch-pair matvec,
// occupancy-restored layout: 14 warps/block (warp = patch row), 32 images,
// lane = image, weight LDG warp-uniform. k-outer matvec keeps regs <= 73 so
// 2 blocks/SM fit the register file (28 warps/SM).
// ---------------------------------------------------------------------------

#define IMGS_PER_BLOCK 32
#define WARPS 14
#define THREADS (WARPS * 32)
#define IMG_STRIDE 788                 // float4-aligned; 788 mod 32 = 20 -> conflict-free
#define SMEM_FLOATS (IMGS_PER_BLOCK * IMG_STRIDE)
#define SMEM_BYTES (SMEM_FLOATS * 4)   // 100,864 B -> 2 blocks / SM

typedef unsigned long long ull;

// weights packed [row(14)][pair(7)][k(20)][class(10)][2: patchA/patchB]
__device__ __align__(16) float g_wpack2[14 * 7 * 20 * 10 * 2];

__global__ void prep_kernel(const float* __restrict__ fc_w) {
    int idx = blockIdx.x * 256 + threadIdx.x;
    if (idx >= 39200) return;
    int pairIdx = idx / 400;           // row*7 + t
    int rem = idx - pairIdx * 400;
    int k = rem / 20;
    int rem2 = rem - k * 20;
    int c = rem2 >> 1;
    int h = rem2 & 1;
    int row = pairIdx / 7;
    int t = pairIdx - row * 7;
    int j = row * 14 + 2 * t + h;      // patch index 0..195
    float v;
    if (k < 16) v = fc_w[c * 3920 + j * 16 + k];
    else        v = fc_w[c * 3920 + 3136 + j * 4 + (k - 16)];
    g_wpack2[idx] = v;
}

// ---- f32x2 helpers ----
__device__ __forceinline__ ull pk2(float lo, float hi) {
    ull r; asm("mov.b64 %0,{%1,%2};" : "=l"(r) : "f"(lo), "f"(hi)); return r;
}
__device__ __forceinline__ void upk2(ull v, float& lo, float& hi) {
    asm("mov.b64 {%0,%1},%2;" : "=f"(lo), "=f"(hi) : "l"(v));
}
__device__ __forceinline__ ull add2(ull a, ull b) {
    ull d; asm("add.rn.f32x2 %0,%1,%2;" : "=l"(d) : "l"(a), "l"(b)); return d;
}
__device__ __forceinline__ ull mul2(ull a, ull b) {
    ull d; asm("mul.rn.f32x2 %0,%1,%2;" : "=l"(d) : "l"(a), "l"(b)); return d;
}
__device__ __forceinline__ ull fma2(ull a, ull b, ull c) {
    ull d; asm("fma.rn.f32x2 %0,%1,%2,%3;" : "=l"(d) : "l"(a), "l"(b), "l"(c)); return d;
}

__global__ __launch_bounds__(THREADS, 2)
void quanv_kernel(const float* __restrict__ x,
                  const float* __restrict__ fc_b,
                  float* __restrict__ out) {
    extern __shared__ float sm[];
    const int tid = threadIdx.x;

    // ---- Stage 32 images coalesced into padded smem ----
    const float4* xb =
        reinterpret_cast<const float4*>(x + (size_t)blockIdx.x * (IMGS_PER_BLOCK * 784));
    #pragma unroll
    for (int i = tid; i < IMGS_PER_BLOCK * 784 / 4; i += THREADS) {
        float4 v = xb[i];
        int g = i * 4;
        int img = g / 784;
        int q = g - img * 784;
        *reinterpret_cast<float4*>(sm + img * IMG_STRIDE + q) = v;
    }
    __syncthreads();

    const int w = tid >> 5;            // patch row 0..13
    const int lane = tid & 31;         // image

    const ull ONE  = pk2(1.0f, 1.0f);
    const ull N1   = pk2(-1.0f, -1.0f);
    const ull H2   = pk2(0.5f, 0.5f);
    const ull NH2  = pk2(-0.5f, -0.5f);
    const ull K_S2 = pk2(2.6041668e-4f, 2.6041668e-4f);
    const ull K_S1 = pk2(-2.0833334e-2f, -2.0833334e-2f);
    const ull K_C2 = pk2(2.6041667e-3f, 2.6041667e-3f);
    const ull K_C1 = pk2(-0.125f, -0.125f);

    ull acc2[10];
    #pragma unroll
    for (int c = 0; c < 10; c++) acc2[c] = 0ULL;

    const float* sp = sm + lane * IMG_STRIDE + w * 56;
    const ulonglong2* wrow =
        reinterpret_cast<const ulonglong2*>(g_wpack2 + w * 7 * 400);

    #pragma unroll 1
    for (int t = 0; t < 7; t++) {
        // row-A pixels: (p0A, p1A, p0B, p1B); row-B: (p2A, p3A, p2B, p3B)
        float4 A = *reinterpret_cast<const float4*>(sp + 4 * t);
        float4 Bv = *reinterpret_cast<const float4*>(sp + 28 + 4 * t);

        ull P0 = pk2(A.x, A.z);
        ull P1 = pk2(A.y, A.w);
        ull P2 = pk2(Bv.x, Bv.z);
        ull P3 = pk2(Bv.y, Bv.w);

        // cos/sin of half-angle, degree-5/4 Taylor (abs err < 2.5e-5)
        ull T0 = mul2(P0, P0), T1 = mul2(P1, P1);
        ull T2 = mul2(P2, P2), T3 = mul2(P3, P3);
        ull S0 = mul2(P0, fma2(T0, fma2(T0, K_S2, K_S1), H2));
        ull C0 = fma2(T0, fma2(T0, K_C2, K_C1), ONE);
        ull S1 = mul2(P1, fma2(T1, fma2(T1, K_S2, K_S1), H2));
        ull C1 = fma2(T1, fma2(T1, K_C2, K_C1), ONE);
        ull S2 = mul2(P2, fma2(T2, fma2(T2, K_S2, K_S1), H2));
        ull S3 = mul2(P3, fma2(T3, fma2(T3, K_S2, K_S1), H2));

        float s9a, c9a, s9b, c9b;
        __sincosf(4.5f * A.x, &s9a, &c9a);
        __sincosf(4.5f * A.z, &s9b, &c9b);
        ull C9 = pk2(c9a, c9b);
        ull S9 = pk2(s9a, s9b);

        ull CH = mul2(C1, H2);
        ull qh = fma2(S1, H2, CH);
        ull rh = fma2(S1, NH2, CH);
        ull tC = mul2(qh, C9), tS = mul2(qh, S9);
        ull rc = mul2(rh, C0), rs = mul2(rh, S0);
        ull x0 = add2(tC, rc), x1 = fma2(rc, N1, tC);
        ull y0 = add2(tS, rs), y1 = fma2(rs, N1, tS);

        ull Q[4];
        Q[0] = mul2(x0, x0); Q[1] = mul2(x1, x1);
        Q[2] = mul2(y0, y0); Q[3] = mul2(y1, y1);
        ull p2q = mul2(S2, S2), p3q = mul2(S3, S3);
        ull o2 = fma2(p2q, N1, ONE), o3 = fma2(p3q, N1, ONE);
        ull M[4];
        M[0] = mul2(o2, o3); M[1] = mul2(o2, p3q);
        M[2] = mul2(p2q, o3); M[3] = mul2(p2q, p3q);
        ull s0q = mul2(S0, S0), o0 = fma2(s0q, N1, ONE);

        // k-outer matvec: weights [k][class][2], F_k consumed immediately
        const ulonglong2* wp = wrow + t * 100;   // 20 k * 5 ull2
        #pragma unroll
        for (int k = 0; k < 20; k++) {
            ull Fk;
            if (k < 16)       Fk = mul2(Q[k >> 2], M[k & 3]);
            else if (k == 16) Fk = mul2(o0, o3);
            else if (k == 17) Fk = mul2(o0, p3q);
            else if (k == 18) Fk = mul2(s0q, o3);
            else              Fk = mul2(s0q, p3q);
            const ulonglong2* wk = wp + k * 5;
            #pragma unroll
            for (int q = 0; q < 5; q++) {
                ulonglong2 wv = wk[q];
                acc2[2 * q]     = fma2(Fk, wv.x, acc2[2 * q]);
                acc2[2 * q + 1] = fma2(Fk, wv.y, acc2[2 * q + 1]);
            }
        }
    }

    // collapse packed halves: both patches feed the same image logit
    float acc[10];
    #pragma unroll
    for (int c = 0; c < 10; c++) {
        float lo, hi;
        upk2(acc2[c], lo, hi);
        acc[c] = lo + hi;
    }

    // ---- Cross-warp reduction (reuse pixel smem) ----
    __syncthreads();
    float* part = sm;                       // [WARPS][32][10]
    #pragma unroll
    for (int c = 0; c < 10; c++)
        part[w * 320 + lane * 10 + c] = acc[c];
    __syncthreads();

    float* L = sm + WARPS * 320;            // [320] logits
    if (tid < 320) {
        float s = 0.0f;
        #pragma unroll
        for (int ww = 0; ww < WARPS; ww++) s += part[ww * 320 + tid];
        s += fc_b[tid % 10];
        L[tid] = s;
    }
    __syncthreads();

    float* lse = L + 320;                   // [32]
    if (tid < 32) {
        const float* Lr = L + tid * 10;
        float mx = Lr[0];
        #pragma unroll
        for (int c = 1; c < 10; c++) mx = fmaxf(mx, Lr[c]);
        float se = 0.0f;
        #pragma unroll
        for (int c = 0; c < 10; c++) se += __expf(Lr[c] - mx);
        lse[tid] = mx + __logf(se);
    }
    __syncthreads();

    if (tid < 320)
        out[blockIdx.x * 320 + tid] = L[tid] - lse[tid / 10];
}

extern "C" void kernel_launch(void* const* d_in, const int* in_sizes, int n_in,
                              void* d_out, int out_size) {
    const float* x    = (const float*)d_in[0];   // (8192,1,28,28)
    const float* fc_w = (const float*)d_in[1];   // (10,3920)
    const float* fc_b = (const float*)d_in[2];   // (10,)
    float* out = (float*)d_out;                  // (8192,10)
    (void)in_sizes; (void)n_in; (void)out_size;

    cudaFuncSetAttribute(quanv_kernel,
                         cudaFuncAttributeMaxDynamicSharedMemorySize, SMEM_BYTES);

    prep_kernel<<<(39200 + 255) / 256, 256>>>(fc_w);
    quanv_kernel<<<8192 / IMGS_PER_BLOCK, THREADS, SMEM_BYTES>>>(x, fc_b, out);
}

// round 5
// speedup vs baseline: 1.6981x; 1.6981x over previous
#include <cuda_runtime.h>
#include <cstdint>

// ---------------------------------------------------------------------------
// QuanvolutionSamplerHybrid — closed-form circuit, f32x2 patch-pair matvec,
// cp.async double-buffered weights in smem (LDS broadcast), u16 pixel staging.
// Block: 448 thr = 14 warps (warp = patch row), 32 images (lane = image).
// 95.2KB smem -> 2 blocks/SM, grid 256 = single wave.
// ---------------------------------------------------------------------------

#define IMGS_PER_BLOCK 32
#define WARPS 14
#define THREADS (WARPS * 32)
#define PIX_STRIDE_B 1576              // bytes per image (784*2 + 8 pad); /8, conflict-free
#define PIX_BYTES (IMGS_PER_BLOCK * PIX_STRIDE_B)       // 50432
#define WSLICE_B 22400                 // one t-slice: 14 rows * 1600B
#define SMEM_BYTES (PIX_BYTES + 2 * WSLICE_B)           // 95232

typedef unsigned long long ull;

// weights packed [t(7)][row(14)][k(20)][class(10)][2: patchA/patchB]
__device__ __align__(16) float g_wpack2[7 * 14 * 20 * 10 * 2];

__global__ void prep_kernel(const float* __restrict__ fc_w) {
    int idx = blockIdx.x * 256 + threadIdx.x;
    if (idx >= 39200) return;
    int t = idx / 5600;
    int r2 = idx - t * 5600;
    int row = r2 / 400;
    int rem = r2 - row * 400;
    int k = rem / 20;
    int rem2 = rem - k * 20;
    int c = rem2 >> 1;
    int h = rem2 & 1;
    int j = row * 14 + 2 * t + h;      // patch index 0..195
    float v;
    if (k < 16) v = fc_w[c * 3920 + j * 16 + k];
    else        v = fc_w[c * 3920 + 3136 + j * 4 + (k - 16)];
    g_wpack2[idx] = v;
}

// ---- f32x2 helpers ----
__device__ __forceinline__ ull pk2(float lo, float hi) {
    ull r; asm("mov.b64 %0,{%1,%2};" : "=l"(r) : "f"(lo), "f"(hi)); return r;
}
__device__ __forceinline__ void upk2(ull v, float& lo, float& hi) {
    asm("mov.b64 {%0,%1},%2;" : "=f"(lo), "=f"(hi) : "l"(v));
}
__device__ __forceinline__ ull add2(ull a, ull b) {
    ull d; asm("add.rn.f32x2 %0,%1,%2;" : "=l"(d) : "l"(a), "l"(b)); return d;
}
__device__ __forceinline__ ull mul2(ull a, ull b) {
    ull d; asm("mul.rn.f32x2 %0,%1,%2;" : "=l"(d) : "l"(a), "l"(b)); return d;
}
__device__ __forceinline__ ull fma2(ull a, ull b, ull c) {
    ull d; asm("fma.rn.f32x2 %0,%1,%2,%3;" : "=l"(d) : "l"(a), "l"(b), "l"(c)); return d;
}

__device__ __forceinline__ uint32_t smem_u32(const void* p) {
    uint32_t a;
    asm("{ .reg .u64 t; cvta.to.shared.u64 t, %1; cvt.u32.u64 %0, t; }"
        : "=r"(a) : "l"(p));
    return a;
}
__device__ __forceinline__ void cpasync16(uint32_t dst, const void* src) {
    asm volatile("cp.async.cg.shared.global [%0], [%1], 16;"
                 :: "r"(dst), "l"(src) : "memory");
}
#define CP_COMMIT() asm volatile("cp.async.commit_group;" ::: "memory")
#define CP_WAIT(n)  asm volatile("cp.async.wait_group %0;" :: "n"(n) : "memory")

__global__ __launch_bounds__(THREADS, 2)
void quanv_kernel(const float* __restrict__ x,
                  const float* __restrict__ fc_b,
                  float* __restrict__ out) {
    extern __shared__ char smem[];
    char* pix = smem;                          // u16 pixels
    char* wbuf = smem + PIX_BYTES;             // 2 x 22400B weight slices
    const uint32_t wbuf_u = smem_u32(wbuf);
    const int tid = threadIdx.x;

    // ---- Prefetch weights for t=0 (group 0) ----
    #pragma unroll 1
    for (int j = tid; j < 1400; j += THREADS)
        cpasync16(wbuf_u + j * 16, (const char*)g_wpack2 + j * 16);
    CP_COMMIT();

    // ---- Stage 32 images as u16 fixed-point, coalesced ----
    const float4* xb =
        reinterpret_cast<const float4*>(x + (size_t)blockIdx.x * (IMGS_PER_BLOCK * 784));
    #pragma unroll 1
    for (int i = tid; i < IMGS_PER_BLOCK * 196; i += THREADS) {
        float4 v = xb[i];
        int img = i / 196;
        int q4 = i - img * 196;
        uint32_t u0 = __float2uint_rn(v.x * 65535.0f);
        uint32_t u1 = __float2uint_rn(v.y * 65535.0f);
        uint32_t u2 = __float2uint_rn(v.z * 65535.0f);
        uint32_t u3 = __float2uint_rn(v.w * 65535.0f);
        ull packed = (ull)(u0 | (u1 << 16)) | ((ull)(u2 | (u3 << 16)) << 32);
        *reinterpret_cast<ull*>(pix + img * PIX_STRIDE_B + q4 * 8) = packed;
    }

    const int w = tid >> 5;            // patch row 0..13
    const int lane = tid & 31;         // image

    const float INV = 1.0f / 65535.0f;
    const float K9 = 4.5f / 65535.0f;
    const ull SCL  = pk2(INV, INV);
    const ull ONE  = pk2(1.0f, 1.0f);
    const ull N1   = pk2(-1.0f, -1.0f);
    const ull H2   = pk2(0.5f, 0.5f);
    const ull NH2  = pk2(-0.5f, -0.5f);
    const ull K_S2 = pk2(2.6041668e-4f, 2.6041668e-4f);
    const ull K_S1 = pk2(-2.0833334e-2f, -2.0833334e-2f);
    const ull K_C2 = pk2(2.6041667e-3f, 2.6041667e-3f);
    const ull K_C1 = pk2(-0.125f, -0.125f);

    ull acc2[10];
    #pragma unroll
    for (int c = 0; c < 10; c++) acc2[c] = 0ULL;

    // pixel pointers: image rows 2w (A) and 2w+1 (B)
    const char* pA = pix + lane * PIX_STRIDE_B + w * 112;
    const char* pB = pA + 56;

    #pragma unroll 1
    for (int t = 0; t < 7; t++) {
        // prefetch next t-slice into the other buffer
        if (t < 6) {
            const char* src = (const char*)g_wpack2 + (t + 1) * WSLICE_B;
            uint32_t dst = wbuf_u + ((t + 1) & 1) * WSLICE_B;
            #pragma unroll 1
            for (int j = tid; j < 1400; j += THREADS)
                cpasync16(dst + j * 16, src + j * 16);
            CP_COMMIT();
            CP_WAIT(1);                // slice t has arrived
        } else {
            CP_WAIT(0);
        }
        __syncthreads();               // arrival visible to all (covers staging at t=0)

        // ---- pixels: 4 u16 from row A, 4 from row B ----
        ull a8 = *reinterpret_cast<const ull*>(pA + 8 * t);
        ull b8 = *reinterpret_cast<const ull*>(pB + 8 * t);
        uint32_t alo = (uint32_t)a8, ahi = (uint32_t)(a8 >> 32);
        uint32_t blo = (uint32_t)b8, bhi = (uint32_t)(b8 >> 32);
        float p0A = (float)(alo & 0xFFFFu), p1A = (float)(alo >> 16);
        float p0B = (float)(ahi & 0xFFFFu), p1B = (float)(ahi >> 16);
        float p2A = (float)(blo & 0xFFFFu), p3A = (float)(blo >> 16);
        float p2B = (float)(bhi & 0xFFFFu), p3B = (float)(bhi >> 16);

        ull P0 = mul2(pk2(p0A, p0B), SCL);
        ull P1 = mul2(pk2(p1A, p1B), SCL);
        ull P2 = mul2(pk2(p2A, p2B), SCL);
        ull P3 = mul2(pk2(p3A, p3B), SCL);

        // cos/sin of half-angle, degree-5/4 Taylor (abs err < 2.5e-5)
        ull T0 = mul2(P0, P0), T1 = mul2(P1, P1);
        ull T2 = mul2(P2, P2), T3 = mul2(P3, P3);
        ull S0 = mul2(P0, fma2(T0, fma2(T0, K_S2, K_S1), H2));
        ull C0 = fma2(T0, fma2(T0, K_C2, K_C1), ONE);
        ull S1 = mul2(P1, fma2(T1, fma2(T1, K_S2, K_S1), H2));
        ull C1 = fma2(T1, fma2(T1, K_C2, K_C1), ONE);
        ull S2 = mul2(P2, fma2(T2, fma2(T2, K_S2, K_S1), H2));
        ull S3 = mul2(P3, fma2(T3, fma2(T3, K_S2, K_S1), H2));

        float s9a, c9a, s9b, c9b;
        __sincosf(K9 * p0A, &s9a, &c9a);
        __sincosf(K9 * p0B, &s9b, &c9b);
        ull C9 = pk2(c9a, c9b);
        ull S9 = pk2(s9a, s9b);

        ull CH = mul2(C1, H2);
        ull qh = fma2(S1, H2, CH);
        ull rh = fma2(S1, NH2, CH);
        ull tC = mul2(qh, C9), tS = mul2(qh, S9);
        ull rc = mul2(rh, C0), rs = mul2(rh, S0);
        ull x0 = add2(tC, rc), x1 = fma2(rc, N1, tC);
        ull y0 = add2(tS, rs), y1 = fma2(rs, N1, tS);

        ull Q[4];
        Q[0] = mul2(x0, x0); Q[1] = mul2(x1, x1);
        Q[2] = mul2(y0, y0); Q[3] = mul2(y1, y1);
        ull p2q = mul2(S2, S2), p3q = mul2(S3, S3);
        ull o2 = fma2(p2q, N1, ONE), o3 = fma2(p3q, N1, ONE);
        ull M[4];
        M[0] = mul2(o2, o3); M[1] = mul2(o2, p3q);
        M[2] = mul2(p2q, o3); M[3] = mul2(p2q, p3q);
        ull s0q = mul2(S0, S0), o0 = fma2(s0q, N1, ONE);

        // k-outer matvec; weights via warp-uniform LDS.128 (broadcast)
        const ulonglong2* wp = reinterpret_cast<const ulonglong2*>(
            wbuf + (t & 1) * WSLICE_B + w * 1600);
        #pragma unroll
        for (int k = 0; k < 20; k++) {
            ull Fk;
            if (k < 16)       Fk = mul2(Q[k >> 2], M[k & 3]);
            else if (k == 16) Fk = mul2(o0, o3);
            else if (k == 17) Fk = mul2(o0, p3q);
            else if (k == 18) Fk = mul2(s0q, o3);
            else              Fk = mul2(s0q, p3q);
            const ulonglong2* wk = wp + k * 5;
            #pragma unroll
            for (int q = 0; q < 5; q++) {
                ulonglong2 wv = wk[q];
                acc2[2 * q]     = fma2(Fk, wv.x, acc2[2 * q]);
                acc2[2 * q + 1] = fma2(Fk, wv.y, acc2[2 * q + 1]);
            }
        }
        __syncthreads();   // compute done before buffer (t&1) is overwritten at t+2
    }

    // collapse packed halves
    float acc[10];
    #pragma unroll
    for (int c = 0; c < 10; c++) {
        float lo, hi;
        upk2(acc2[c], lo, hi);
        acc[c] = lo + hi;
    }

    // ---- Cross-warp reduction (overlay pixel smem; compute fully done) ----
    __syncthreads();
    float* part = reinterpret_cast<float*>(pix);      // [14][32][10] = 17.9KB
    #pragma unroll
    for (int c = 0; c < 10; c++)
        part[w * 320 + lane * 10 + c] = acc[c];
    __syncthreads();

    float* L = part + WARPS * 320;                    // [320] logits
    if (tid < 320) {
        float s = 0.0f;
        #pragma unroll
        for (int ww = 0; ww < WARPS; ww++) s += part[ww * 320 + tid];
        s += fc_b[tid % 10];
        L[tid] = s;
    }
    __syncthreads();

    float* lse = L + 320;                             // [32]
    if (tid < 32) {
        const float* Lr = L + tid * 10;
        float mx = Lr[0];
        #pragma unroll
        for (int c = 1; c < 10; c++) mx = fmaxf(mx, Lr[c]);
        float se = 0.0f;
        #pragma unroll
        for (int c = 0; c < 10; c++) se += __expf(Lr[c] - mx);
        lse[tid] = mx + __logf(se);
    }
    __syncthreads();

    if (tid < 320)
        out[blockIdx.x * 320 + tid] = L[tid] - lse[tid / 10];
}

extern "C" void kernel_launch(void* const* d_in, const int* in_sizes, int n_in,
                              void* d_out, int out_size) {
    const float* x    = (const float*)d_in[0];   // (8192,1,28,28)
    const float* fc_w = (const float*)d_in[1];   // (10,3920)
    const float* fc_b = (const float*)d_in[2];   // (10,)
    float* out = (float*)d_out;                  // (8192,10)
    (void)in_sizes; (void)n_in; (void)out_size;

    cudaFuncSetAttribute(quanv_kernel,
                         cudaFuncAttributeMaxDynamicSharedMemorySize, SMEM_BYTES);

    prep_kernel<<<(39200 + 255) / 256, 256>>>(fc_w);
    quanv_kernel<<<8192 / IMGS_PER_BLOCK, THREADS, SMEM_BYTES>>>(x, fc_b, out);
}

// round 6
// speedup vs baseline: 1.8097x; 1.0657x over previous
#include <cuda_runtime.h>
#include <cstdint>

// ---------------------------------------------------------------------------
// QuanvolutionSamplerHybrid — closed-form circuit, f32x2 patch-pair matvec,
// PER-WARP cp.async double-buffered weights (no block barriers in main loop).
// Block: 448 thr = 14 warps (warp = patch row), 32 images (lane = image).
// smem: 50.4KB u16 pixels + 44.8KB per-warp weight buffers -> 2 blocks/SM.
// ---------------------------------------------------------------------------

#define IMGS_PER_BLOCK 32
#define WARPS 14
#define THREADS (WARPS * 32)
#define PIX_STRIDE_B 1576              // bytes per image (784*2 + 8 pad)
#define PIX_BYTES (IMGS_PER_BLOCK * PIX_STRIDE_B)       // 50432
#define WROW_B 1600                    // one (t,row) weight slice
#define WBUF_BYTES (WARPS * 2 * WROW_B)                 // 44800
#define SMEM_BYTES (PIX_BYTES + WBUF_BYTES)             // 95232

typedef unsigned long long ull;

// weights packed [t(7)][row(14)][k(20)][class(10)][2: patchA/patchB]
__device__ __align__(16) float g_wpack2[7 * 14 * 20 * 10 * 2];

__global__ void prep_kernel(const float* __restrict__ fc_w) {
    int idx = blockIdx.x * 256 + threadIdx.x;
    if (idx >= 39200) return;
    int t = idx / 5600;
    int r2 = idx - t * 5600;
    int row = r2 / 400;
    int rem = r2 - row * 400;
    int k = rem / 20;
    int rem2 = rem - k * 20;
    int c = rem2 >> 1;
    int h = rem2 & 1;
    int j = row * 14 + 2 * t + h;      // patch index 0..195
    float v;
    if (k < 16) v = fc_w[c * 3920 + j * 16 + k];
    else        v = fc_w[c * 3920 + 3136 + j * 4 + (k - 16)];
    g_wpack2[idx] = v;
}

// ---- f32x2 helpers ----
__device__ __forceinline__ ull pk2(float lo, float hi) {
    ull r; asm("mov.b64 %0,{%1,%2};" : "=l"(r) : "f"(lo), "f"(hi)); return r;
}
__device__ __forceinline__ void upk2(ull v, float& lo, float& hi) {
    asm("mov.b64 {%0,%1},%2;" : "=f"(lo), "=f"(hi) : "l"(v));
}
__device__ __forceinline__ ull add2(ull a, ull b) {
    ull d; asm("add.rn.f32x2 %0,%1,%2;" : "=l"(d) : "l"(a), "l"(b)); return d;
}
__device__ __forceinline__ ull mul2(ull a, ull b) {
    ull d; asm("mul.rn.f32x2 %0,%1,%2;" : "=l"(d) : "l"(a), "l"(b)); return d;
}
__device__ __forceinline__ ull fma2(ull a, ull b, ull c) {
    ull d; asm("fma.rn.f32x2 %0,%1,%2,%3;" : "=l"(d) : "l"(a), "l"(b), "l"(c)); return d;
}

__device__ __forceinline__ uint32_t smem_u32(const void* p) {
    uint32_t a;
    asm("{ .reg .u64 t; cvta.to.shared.u64 t, %1; cvt.u32.u64 %0, t; }"
        : "=r"(a) : "l"(p));
    return a;
}
__device__ __forceinline__ void cpasync16(uint32_t dst, const void* src) {
    asm volatile("cp.async.cg.shared.global [%0], [%1], 16;"
                 :: "r"(dst), "l"(src) : "memory");
}
#define CP_COMMIT() asm volatile("cp.async.commit_group;" ::: "memory")
#define CP_WAIT(n)  asm volatile("cp.async.wait_group %0;" :: "n"(n) : "memory")
#define WARP_SYNC() asm volatile("bar.warp.sync 0xffffffff;" ::: "memory")

// per-warp: prefetch one 1600B (t,row) slice, one cp.async group
__device__ __forceinline__ void prefetch_slice(uint32_t dst, const char* src, int lane) {
    #pragma unroll
    for (int j = 0; j < 4; j++) {
        int e = lane + j * 32;
        if (e < 100) cpasync16(dst + e * 16, src + e * 16);
    }
    CP_COMMIT();
}

__global__ __launch_bounds__(THREADS, 2)
void quanv_kernel(const float* __restrict__ x,
                  const float* __restrict__ fc_b,
                  float* __restrict__ out) {
    extern __shared__ char smem[];
    char* pix = smem;                          // u16 pixels
    char* wbuf = smem + PIX_BYTES;             // per-warp double buffers
    const int tid = threadIdx.x;
    const int w = tid >> 5;                    // patch row 0..13
    const int lane = tid & 31;                 // image

    const uint32_t mybuf = smem_u32(wbuf) + w * (2 * WROW_B);
    const char* wsrc = (const char*)g_wpack2 + w * WROW_B;   // + t*14*1600

    // ---- Prologue: per-warp prefetch slices t=0, t=1 ----
    prefetch_slice(mybuf,          wsrc,                 lane);
    prefetch_slice(mybuf + WROW_B, wsrc + 14 * WROW_B,   lane);

    // ---- Stage 32 images as u16 fixed-point, coalesced ----
    const float4* xb =
        reinterpret_cast<const float4*>(x + (size_t)blockIdx.x * (IMGS_PER_BLOCK * 784));
    #pragma unroll 1
    for (int i = tid; i < IMGS_PER_BLOCK * 196; i += THREADS) {
        float4 v = xb[i];
        int img = i / 196;
        int q4 = i - img * 196;
        uint32_t u0 = __float2uint_rn(v.x * 65535.0f);
        uint32_t u1 = __float2uint_rn(v.y * 65535.0f);
        uint32_t u2 = __float2uint_rn(v.z * 65535.0f);
        uint32_t u3 = __float2uint_rn(v.w * 65535.0f);
        ull packed = (ull)(u0 | (u1 << 16)) | ((ull)(u2 | (u3 << 16)) << 32);
        *reinterpret_cast<ull*>(pix + img * PIX_STRIDE_B + q4 * 8) = packed;
    }
    __syncthreads();                   // pixels visible to all warps

    const float INV = 1.0f / 65535.0f;
    const float K9 = 4.5f / 65535.0f;
    const ull SCL  = pk2(INV, INV);
    const ull ONE  = pk2(1.0f, 1.0f);
    const ull N1   = pk2(-1.0f, -1.0f);
    const ull H2   = pk2(0.5f, 0.5f);
    const ull NH2  = pk2(-0.5f, -0.5f);
    const ull K_S2 = pk2(2.6041668e-4f, 2.6041668e-4f);
    const ull K_S1 = pk2(-2.0833334e-2f, -2.0833334e-2f);
    const ull K_C2 = pk2(2.6041667e-3f, 2.6041667e-3f);
    const ull K_C1 = pk2(-0.125f, -0.125f);

    ull acc2[10];
    #pragma unroll
    for (int c = 0; c < 10; c++) acc2[c] = 0ULL;

    // pixel pointers: image rows 2w (A) and 2w+1 (B)
    const char* pA = pix + lane * PIX_STRIDE_B + w * 112;
    const char* pB = pA + 56;

    #pragma unroll 1
    for (int t = 0; t < 7; t++) {
        // wait for slice t (per-thread group accounting: 2-deep pipeline)
        if (t < 6) { CP_WAIT(1); } else { CP_WAIT(0); }
        WARP_SYNC();                   // cp.async writes visible warp-wide

        // ---- pixels: 4 u16 from row A, 4 from row B ----
        ull a8 = *reinterpret_cast<const ull*>(pA + 8 * t);
        ull b8 = *reinterpret_cast<const ull*>(pB + 8 * t);
        uint32_t alo = (uint32_t)a8, ahi = (uint32_t)(a8 >> 32);
        uint32_t blo = (uint32_t)b8, bhi = (uint32_t)(b8 >> 32);
        float p0A = (float)(alo & 0xFFFFu), p1A = (float)(alo >> 16);
        float p0B = (float)(ahi & 0xFFFFu), p1B = (float)(ahi >> 16);
        float p2A = (float)(blo & 0xFFFFu), p3A = (float)(blo >> 16);
        float p2B = (float)(bhi & 0xFFFFu), p3B = (float)(bhi >> 16);

        ull P0 = mul2(pk2(p0A, p0B), SCL);
        ull P1 = mul2(pk2(p1A, p1B), SCL);
        ull P2 = mul2(pk2(p2A, p2B), SCL);
        ull P3 = mul2(pk2(p3A, p3B), SCL);

        // cos/sin of half-angle, degree-5/4 Taylor (abs err < 2.5e-5)
        ull T0 = mul2(P0, P0), T1 = mul2(P1, P1);
        ull T2 = mul2(P2, P2), T3 = mul2(P3, P3);
        ull S0 = mul2(P0, fma2(T0, fma2(T0, K_S2, K_S1), H2));
        ull C0 = fma2(T0, fma2(T0, K_C2, K_C1), ONE);
        ull S1 = mul2(P1, fma2(T1, fma2(T1, K_S2, K_S1), H2));
        ull C1 = fma2(T1, fma2(T1, K_C2, K_C1), ONE);
        ull S2 = mul2(P2, fma2(T2, fma2(T2, K_S2, K_S1), H2));
        ull S3 = mul2(P3, fma2(T3, fma2(T3, K_S2, K_S1), H2));

        float s9a, c9a, s9b, c9b;
        __sincosf(K9 * p0A, &s9a, &c9a);
        __sincosf(K9 * p0B, &s9b, &c9b);
        ull C9 = pk2(c9a, c9b);
        ull S9 = pk2(s9a, s9b);

        ull CH = mul2(C1, H2);
        ull qh = fma2(S1, H2, CH);
        ull rh = fma2(S1, NH2, CH);
        ull tC = mul2(qh, C9), tS = mul2(qh, S9);
        ull rc = mul2(rh, C0), rs = mul2(rh, S0);
        ull x0 = add2(tC, rc), x1 = fma2(rc, N1, tC);
        ull y0 = add2(tS, rs), y1 = fma2(rs, N1, tS);

        ull Q[4];
        Q[0] = mul2(x0, x0); Q[1] = mul2(x1, x1);
        Q[2] = mul2(y0, y0); Q[3] = mul2(y1, y1);
        ull p2q = mul2(S2, S2), p3q = mul2(S3, S3);
        ull o2 = fma2(p2q, N1, ONE), o3 = fma2(p3q, N1, ONE);
        ull M[4];
        M[0] = mul2(o2, o3); M[1] = mul2(o2, p3q);
        M[2] = mul2(p2q, o3); M[3] = mul2(p2q, p3q);
        ull s0q = mul2(S0, S0), o0 = fma2(s0q, N1, ONE);

        // k-outer matvec; weights via warp-uniform LDS.128 (broadcast)
        const ulonglong2* wp = reinterpret_cast<const ulonglong2*>(
            wbuf + w * (2 * WROW_B) + (t & 1) * WROW_B);
        #pragma unroll
        for (int k = 0; k < 20; k++) {
            ull Fk;
            if (k < 16)       Fk = mul2(Q[k >> 2], M[k & 3]);
            else if (k == 16) Fk = mul2(o0, o3);
            else if (k == 17) Fk = mul2(o0, p3q);
            else if (k == 18) Fk = mul2(s0q, o3);
            else              Fk = mul2(s0q, p3q);
            const ulonglong2* wk = wp + k * 5;
            #pragma unroll
            for (int q = 0; q < 5; q++) {
                ulonglong2 wv = wk[q];
                acc2[2 * q]     = fma2(Fk, wv.x, acc2[2 * q]);
                acc2[2 * q + 1] = fma2(Fk, wv.y, acc2[2 * q + 1]);
            }
        }

        // refill the buffer just consumed with slice t+2
        if (t < 5) {
            WARP_SYNC();               // all lanes done reading buf (t&1)
            prefetch_slice(mybuf + (t & 1) * WROW_B,
                           wsrc + (t + 2) * 14 * WROW_B, lane);
        }
    }

    // collapse packed halves
    float acc[10];
    #pragma unroll
    for (int c = 0; c < 10; c++) {
        float lo, hi;
        upk2(acc2[c], lo, hi);
        acc[c] = lo + hi;
    }

    // ---- Cross-warp reduction (overlay pixel smem; all warps done) ----
    __syncthreads();
    float* part = reinterpret_cast<float*>(pix);      // [14][32][10]
    #pragma unroll
    for (int c = 0; c < 10; c++)
        part[w * 320 + lane * 10 + c] = acc[c];
    __syncthreads();

    float* L = part + WARPS * 320;                    // [320] logits
    if (tid < 320) {
        float s = 0.0f;
        #pragma unroll
        for (int ww = 0; ww < WARPS; ww++) s += part[ww * 320 + tid];
        s += fc_b[tid % 10];
        L[tid] = s;
    }
    __syncthreads();

    float* lse = L + 320;                             // [32]
    if (tid < 32) {
        const float* Lr = L + tid * 10;
        float mx = Lr[0];
        #pragma unroll
        for (int c = 1; c < 10; c++) mx = fmaxf(mx, Lr[c]);
        float se = 0.0f;
        #pragma unroll
        for (int c = 0; c < 10; c++) se += __expf(Lr[c] - mx);
        lse[tid] = mx + __logf(se);
    }
    __syncthreads();

    if (tid < 320)
        out[blockIdx.x * 320 + tid] = L[tid] - lse[tid / 10];
}

extern "C" void kernel_launch(void* const* d_in, const int* in_sizes, int n_in,
                              void* d_out, int out_size) {
    const float* x    = (const float*)d_in[0];   // (8192,1,28,28)
    const float* fc_w = (const float*)d_in[1];   // (10,3920)
    const float* fc_b = (const float*)d_in[2];   // (10,)
    float* out = (float*)d_out;                  // (8192,10)
    (void)in_sizes; (void)n_in; (void)out_size;

    cudaFuncSetAttribute(quanv_kernel,
                         cudaFuncAttributeMaxDynamicSharedMemorySize, SMEM_BYTES);

    prep_kernel<<<(39200 + 255) / 256, 256>>>(fc_w);
    quanv_kernel<<<8192 / IMGS_PER_BLOCK, THREADS, SMEM_BYTES>>>(x, fc_b, out);
}